// round 1
// baseline (speedup 1.0000x reference)
#include <cuda_runtime.h>

// Weighted 4D LUT interpolation with 4x spatial upscale.
// Shapes (hardcoded from reference): L=4, D=17, S=4, B=4, H=256, W=256, BINSIZE=16.
// lut:    [4,17,17,17,17,4,4] f32  (d_in[0], 5,345,344 elems)
// tri:    [24,4]              f32  (d_in[1], unused by reference math)
// weight: [4,4,256,256]       f32  (d_in[2])
// x:      [4,1,256,256]       f32  (d_in[3])
// scale:  scalar (=4)              (d_in[4], hardcoded)
// out:    [4,1,1024,1024]     f32

#define NPIX (4 * 256 * 256)
#define D4   83521   // 17^4

__global__ void __launch_bounds__(256) w4dlut_kernel(
    const float* __restrict__ lut,
    const float* __restrict__ weight,
    const float* __restrict__ x,
    float* __restrict__ out)
{
    int g = blockIdx.x * 256 + threadIdx.x;
    int w = g & 255;
    int h = (g >> 8) & 255;
    int b = g >> 16;

    // reflect padding (mode='reflect', excludes edge): index H maps to H-2
    int h1 = (h + 1 < 256) ? h + 1 : 254;
    int w1 = (w + 1 < 256) ? w + 1 : 254;

    const float* xb = x + b * 65536;
    float pv[4];
    pv[0] = xb[h  * 256 + w ];
    pv[1] = xb[h  * 256 + w1];
    pv[2] = xb[h1 * 256 + w ];
    pv[3] = xb[h1 * 256 + w1];

    float f[4];
    int   base[4];
#pragma unroll
    for (int d = 0; d < 4; ++d) {
        float t  = pv[d] * (1.0f / 16.0f);
        float bf = floorf(t);
        f[d] = t - bf;
        int bi = (int)bf;
        bi = min(max(bi, 0), 15);   // clip to D-2
        base[d] = bi;
    }

    // stable descending rank (matches jnp.argsort(-frac): ties keep lower dim first)
    int rank[4];
#pragma unroll
    for (int d = 0; d < 4; ++d) {
        int r = 0;
#pragma unroll
        for (int e = 0; e < 4; ++e)
            r += (f[e] > f[d]) || (f[e] == f[d] && e < d);
        rank[d] = r;
    }

    // sorted fracs and per-sorted-position dim stride (for incremental flat index)
    const int strides[4] = {4913, 289, 17, 1};  // 17^3, 17^2, 17, 1
    float sf[4];
    int   sd[4];
#pragma unroll
    for (int r = 0; r < 4; ++r) {
        float v = 0.0f; int s = 0;
#pragma unroll
        for (int d = 0; d < 4; ++d) {
            if (rank[d] == r) { v = f[d]; s = strides[d]; }
        }
        sf[r] = v; sd[r] = s;
    }

    float wts[5];
    wts[0] = 1.0f - sf[0];
    wts[1] = sf[0] - sf[1];
    wts[2] = sf[1] - sf[2];
    wts[3] = sf[2] - sf[3];
    wts[4] = sf[3];

    int flat = ((base[0] * 17 + base[1]) * 17 + base[2]) * 17 + base[3];

    float wg[4];
#pragma unroll
    for (int l = 0; l < 4; ++l)
        wg[l] = weight[((b * 4 + l) * 256 + h) * 256 + w];

    float acc[16];
#pragma unroll
    for (int i = 0; i < 16; ++i) acc[i] = 0.0f;

    // 5 simplex vertices x 4 LUTs: 20 gathers of 64B each
#pragma unroll
    for (int k = 0; k < 5; ++k) {
        if (k) flat += sd[k - 1];
#pragma unroll
        for (int l = 0; l < 4; ++l) {
            float c = wts[k] * wg[l];
            const float4* pp =
                (const float4*)(lut + ((size_t)(l * D4 + flat)) * 16);
#pragma unroll
            for (int q = 0; q < 4; ++q) {
                float4 v = __ldg(pp + q);
                acc[q * 4 + 0] = fmaf(c, v.x, acc[q * 4 + 0]);
                acc[q * 4 + 1] = fmaf(c, v.y, acc[q * 4 + 1]);
                acc[q * 4 + 2] = fmaf(c, v.z, acc[q * 4 + 2]);
                acc[q * 4 + 3] = fmaf(c, v.w, acc[q * 4 + 3]);
            }
        }
    }

    // out[b, 0, h*4+sy, w*4+sx] = acc[sy*4+sx]; rows are 16B-aligned float4s
    float4* o = (float4*)(out + (((size_t)b * 1024 + h * 4) * 1024 + w * 4));
#pragma unroll
    for (int sy = 0; sy < 4; ++sy) {
        float4 v = make_float4(acc[sy * 4 + 0], acc[sy * 4 + 1],
                               acc[sy * 4 + 2], acc[sy * 4 + 3]);
        o[sy * 256] = v;  // row stride = 1024 floats = 256 float4
    }
}

extern "C" void kernel_launch(void* const* d_in, const int* in_sizes, int n_in,
                              void* d_out, int out_size)
{
    const float* lut    = (const float*)d_in[0];
    const float* weight = (const float*)d_in[2];
    const float* x      = (const float*)d_in[3];
    float* out          = (float*)d_out;

    w4dlut_kernel<<<NPIX / 256, 256>>>(lut, weight, x, out);
}

// round 2
// speedup vs baseline: 2.2102x; 2.2102x over previous
#include <cuda_runtime.h>

// Weighted 4D LUT interpolation with 4x spatial upscale.
// Shapes: L=4, D=17, S=4, B=4, H=256, W=256, BINSIZE=16.
// lut:    [4,17,17,17,17,4,4] f32  (d_in[0])
// weight: [4,4,256,256]       f32  (d_in[2])
// x:      [4,1,256,256]       f32  (d_in[3])
// out:    [4,1,1024,1024]     f32
//
// Cooperative-quad layout: 4 consecutive lanes own one pixel; lane q loads
// quarter q (16B) of every 64B LUT row, so one warp-level LDG.128 touches
// ~8 distinct 128B lines (8 pixels' rows) instead of 32 -> 4x fewer L1tex
// wavefronts. Lane q accumulates the sy=q output row.

#define NPIX (4 * 256 * 256)
#define D4   83521   // 17^4

__global__ void __launch_bounds__(256) w4dlut_kernel(
    const float* __restrict__ lut,
    const float* __restrict__ weight,
    const float* __restrict__ x,
    float* __restrict__ out)
{
    int t  = blockIdx.x * 256 + threadIdx.x;
    int lq = t & 3;        // quarter (= sy) this lane owns
    int g  = t >> 2;       // pixel id
    int w  = g & 255;
    int h  = (g >> 8) & 255;
    int b  = g >> 16;

    // reflect padding (excludes edge): index 256 maps to 254
    int h1 = (h + 1 < 256) ? h + 1 : 254;
    int w1 = (w + 1 < 256) ? w + 1 : 254;

    const float* xb = x + b * 65536;
    float pv[4];
    pv[0] = xb[h  * 256 + w ];
    pv[1] = xb[h  * 256 + w1];
    pv[2] = xb[h1 * 256 + w ];
    pv[3] = xb[h1 * 256 + w1];

    float f[4];
    int   base[4];
#pragma unroll
    for (int d = 0; d < 4; ++d) {
        float tt = pv[d] * (1.0f / 16.0f);
        float bf = floorf(tt);
        f[d] = tt - bf;
        int bi = (int)bf;
        bi = min(max(bi, 0), 15);   // clip to D-2
        base[d] = bi;
    }

    // stable descending rank (matches jnp.argsort(-frac))
    int rank[4];
#pragma unroll
    for (int d = 0; d < 4; ++d) {
        int r = 0;
#pragma unroll
        for (int e = 0; e < 4; ++e)
            r += (f[e] > f[d]) || (f[e] == f[d] && e < d);
        rank[d] = r;
    }

    const int strides[4] = {4913, 289, 17, 1};  // 17^3, 17^2, 17, 1
    float sf[4];
    int   sd[4];
#pragma unroll
    for (int r = 0; r < 4; ++r) {
        float v = 0.0f; int s = 0;
#pragma unroll
        for (int d = 0; d < 4; ++d) {
            if (rank[d] == r) { v = f[d]; s = strides[d]; }
        }
        sf[r] = v; sd[r] = s;
    }

    float wts[5];
    wts[0] = 1.0f - sf[0];
    wts[1] = sf[0] - sf[1];
    wts[2] = sf[1] - sf[2];
    wts[3] = sf[2] - sf[3];
    wts[4] = sf[3];

    int flat = ((base[0] * 17 + base[1]) * 17 + base[2]) * 17 + base[3];

    float wg[4];
#pragma unroll
    for (int l = 0; l < 4; ++l)
        wg[l] = weight[((b * 4 + l) * 256 + h) * 256 + w];

    // lane lq accumulates s-values [lq*4 .. lq*4+3]  (sy = lq, sx = 0..3)
    float a0 = 0.0f, a1 = 0.0f, a2 = 0.0f, a3 = 0.0f;

#pragma unroll
    for (int k = 0; k < 5; ++k) {
        if (k) flat += sd[k - 1];
#pragma unroll
        for (int l = 0; l < 4; ++l) {
            float c = wts[k] * wg[l];
            const float4* pp =
                (const float4*)(lut + ((size_t)(l * D4 + flat)) * 16) + lq;
            float4 v = __ldg(pp);
            a0 = fmaf(c, v.x, a0);
            a1 = fmaf(c, v.y, a1);
            a2 = fmaf(c, v.z, a2);
            a3 = fmaf(c, v.w, a3);
        }
    }

    // lane lq writes out[b, 0, h*4+lq, w*4 .. w*4+3]
    float4* o = (float4*)(out + (((size_t)b * 1024 + h * 4 + lq) * 1024 + w * 4));
    *o = make_float4(a0, a1, a2, a3);
}

extern "C" void kernel_launch(void* const* d_in, const int* in_sizes, int n_in,
                              void* d_out, int out_size)
{
    const float* lut    = (const float*)d_in[0];
    const float* weight = (const float*)d_in[2];
    const float* x      = (const float*)d_in[3];
    float* out          = (float*)d_out;

    w4dlut_kernel<<<(NPIX * 4) / 256, 256>>>(lut, weight, x, out);
}